// round 2
// baseline (speedup 1.0000x reference)
#include <cuda_runtime.h>
#include <math.h>

#define RNK 8
#define DIM 2048
#define BSZ 8
#define SEQ 2048
#define ROWS_PER_BLOCK 16
#define SCALING 2.0f   /* 16 / r = 16/8 */

// ---- scratch (no allocations allowed; __device__ globals) ----
__device__ float g_gate[BSZ * 4];
__device__ float g_A[BSZ * RNK * DIM];   // 512 KB
__device__ float g_B[BSZ * RNK * DIM];   // 512 KB

// ============================================================
// Kernel 1: gating MLP.  One block, warp-per-batch.
//   LN(ctr[32]) -> W1[60,32]+b1, relu -> W2[4,60]+b2 -> softmax
// ============================================================
__global__ void gate_kernel(const float* __restrict__ ctr,
                            const float* __restrict__ gamma,
                            const float* __restrict__ beta,
                            const float* __restrict__ W1,
                            const float* __restrict__ b1,
                            const float* __restrict__ W2,
                            const float* __restrict__ b2) {
    __shared__ float z_s[BSZ][32];
    __shared__ float h_s[BSZ][60];
    int w = threadIdx.x >> 5;      // batch
    int lane = threadIdx.x & 31;   // ctr_out index (=32)
    if (w >= BSZ) return;

    float v = ctr[w * 32 + lane];
    float m = v;
    #pragma unroll
    for (int off = 16; off; off >>= 1) m += __shfl_xor_sync(0xffffffffu, m, off);
    m *= (1.0f / 32.0f);
    float d = v - m;
    float s = d * d;
    #pragma unroll
    for (int off = 16; off; off >>= 1) s += __shfl_xor_sync(0xffffffffu, s, off);
    s *= (1.0f / 32.0f);
    float z = d * rsqrtf(s + 1e-5f) * gamma[lane] + beta[lane];
    z_s[w][lane] = z;
    __syncwarp();

    for (int j = lane; j < 60; j += 32) {
        float acc = b1[j];
        #pragma unroll
        for (int c = 0; c < 32; c++) acc += z_s[w][c] * W1[j * 32 + c];
        h_s[w][j] = fmaxf(acc, 0.0f);
    }
    __syncwarp();

    if (lane == 0) {
        float g[4];
        #pragma unroll
        for (int k = 0; k < 4; k++) {
            float acc = b2[k];
            for (int j = 0; j < 60; j++) acc += h_s[w][j] * W2[k * 60 + j];
            g[k] = acc;
        }
        float mx = fmaxf(fmaxf(g[0], g[1]), fmaxf(g[2], g[3]));
        float e0 = expf(g[0] - mx), e1 = expf(g[1] - mx);
        float e2 = expf(g[2] - mx), e3 = expf(g[3] - mx);
        float inv = 1.0f / (e0 + e1 + e2 + e3);
        g_gate[w * 4 + 0] = e0 * inv;
        g_gate[w * 4 + 1] = e1 * inv;
        g_gate[w * 4 + 2] = e2 * inv;
        g_gate[w * 4 + 3] = e3 * inv;
    }
}

// ============================================================
// Kernel 2: per-sample adapters.
//   A[b][j] = dot4(gate[b], Wa[j]);  B[b][j] = dot4(gate[b], Wb[j])
//   j in [0, R*DIM); Wa/Wb rows are 4 contiguous floats (float4).
// ============================================================
__global__ void ab_kernel(const float* __restrict__ Wa,
                          const float* __restrict__ Wb) {
    int idx = blockIdx.x * blockDim.x + threadIdx.x;  // over 2*16384
    if (idx >= 2 * RNK * DIM) return;
    int j = idx & (RNK * DIM - 1);
    const float4* Wrow = (idx < RNK * DIM) ? (const float4*)Wa : (const float4*)Wb;
    float* dst = (idx < RNK * DIM) ? g_A : g_B;
    float4 w4 = Wrow[j];
    #pragma unroll
    for (int b = 0; b < BSZ; b++) {
        float4 g4 = ((const float4*)g_gate)[b];
        dst[b * RNK * DIM + j] = w4.x * g4.x + w4.y * g4.y + w4.z * g4.z + w4.w * g4.w;
    }
}

// ============================================================
// Kernel 3: the big one.  out[b,s,:] = SCALING * (x[b,s,:] @ A[b]^T) @ B[b]
//   1024 blocks x 512 threads; block = (batch, 16-row tile).
//   A[b] staged in 64 KB dynamic smem; B[b] register-tiled in phase 2.
// ============================================================
extern __shared__ float As[];  // RNK*DIM = 16384 floats = 64 KB

__global__ __launch_bounds__(512)
void main_kernel(const float* __restrict__ x, float* __restrict__ out) {
    __shared__ float xa_s[ROWS_PER_BLOCK][RNK];

    int b = blockIdx.x >> 7;            // / (SEQ/ROWS_PER_BLOCK = 128)
    int tile = blockIdx.x & 127;
    int row0 = tile * ROWS_PER_BLOCK;

    // ---- cooperative load of A[b] into smem (float4, coalesced) ----
    {
        const float4* src = (const float4*)(g_A + b * RNK * DIM);
        float4* dst = (float4*)As;
        #pragma unroll
        for (int i = threadIdx.x; i < (RNK * DIM) / 4; i += 512) dst[i] = src[i];
    }
    __syncthreads();

    int warp = threadIdx.x >> 5;
    int lane = threadIdx.x & 31;

    // ---- phase 1: warp-per-row, xa[row][r] = x_row . A[r] ----
    {
        const float* xrow = x + ((size_t)b * SEQ + row0 + warp) * DIM;
        const float4* x4 = (const float4*)xrow;
        float acc[RNK];
        #pragma unroll
        for (int r = 0; r < RNK; r++) acc[r] = 0.0f;
        #pragma unroll 4
        for (int k = 0; k < 16; k++) {
            int d4 = k * 32 + lane;              // float4 index in [0,512)
            float4 xv = x4[d4];
            #pragma unroll
            for (int r = 0; r < RNK; r++) {
                float4 a = ((const float4*)(As + r * DIM))[d4];
                acc[r] += xv.x * a.x + xv.y * a.y + xv.z * a.z + xv.w * a.w;
            }
        }
        #pragma unroll
        for (int r = 0; r < RNK; r++) {
            #pragma unroll
            for (int off = 16; off; off >>= 1)
                acc[r] += __shfl_xor_sync(0xffffffffu, acc[r], off);
        }
        if (lane == 0) {
            #pragma unroll
            for (int r = 0; r < RNK; r++) xa_s[warp][r] = acc[r];
        }
    }
    __syncthreads();

    // ---- phase 2: thread owns 4 output cols; B reg-tiled; 16 coalesced rows ----
    {
        const float* Bb = g_B + b * RNK * DIM;
        float4 Br[RNK];
        #pragma unroll
        for (int r = 0; r < RNK; r++)
            Br[r] = ((const float4*)(Bb + r * DIM))[threadIdx.x];

        #pragma unroll
        for (int i = 0; i < ROWS_PER_BLOCK; i++) {
            float4 o = make_float4(0.f, 0.f, 0.f, 0.f);
            #pragma unroll
            for (int r = 0; r < RNK; r++) {
                float xa = xa_s[i][r];
                o.x += xa * Br[r].x;
                o.y += xa * Br[r].y;
                o.z += xa * Br[r].z;
                o.w += xa * Br[r].w;
            }
            o.x *= SCALING; o.y *= SCALING; o.z *= SCALING; o.w *= SCALING;
            ((float4*)(out + ((size_t)b * SEQ + row0 + i) * DIM))[threadIdx.x] = o;
        }
    }
}

// ============================================================
// launcher
// ============================================================
extern "C" void kernel_launch(void* const* d_in, const int* in_sizes, int n_in,
                              void* d_out, int out_size) {
    const float* x     = (const float*)d_in[0];
    const float* ctr   = (const float*)d_in[1];
    const float* gamma = (const float*)d_in[2];
    const float* beta  = (const float*)d_in[3];
    const float* W1    = (const float*)d_in[4];
    const float* b1    = (const float*)d_in[5];
    const float* W2    = (const float*)d_in[6];
    const float* b2    = (const float*)d_in[7];
    const float* Wa    = (const float*)d_in[8];
    const float* Wb    = (const float*)d_in[9];
    float* out = (float*)d_out;

    static bool attr_set = false;
    if (!attr_set) {
        cudaFuncSetAttribute(main_kernel,
                             cudaFuncAttributeMaxDynamicSharedMemorySize,
                             RNK * DIM * (int)sizeof(float));
        attr_set = true;
    }

    gate_kernel<<<1, 256>>>(ctr, gamma, beta, W1, b1, W2, b2);
    ab_kernel<<<(2 * RNK * DIM + 255) / 256, 256>>>(Wa, Wb);
    main_kernel<<<BSZ * (SEQ / ROWS_PER_BLOCK), 512, RNK * DIM * sizeof(float)>>>(x, out);
}

// round 4
// speedup vs baseline: 1.1252x; 1.1252x over previous
#include <cuda_runtime.h>
#include <math.h>

#define RNK 8
#define DIM 2048
#define BSZ 8
#define SEQ 2048
#define ROWS_CHUNK 32
#define CHUNKS 2
#define ROWS_PER_BLOCK (ROWS_CHUNK * CHUNKS)   /* 64 */
#define SCALING 2.0f   /* 16 / r = 16/8 */

// ---- scratch (no allocations allowed; __device__ globals) ----
__device__ float g_A[BSZ * RNK * DIM];   // 512 KB
__device__ float g_B[BSZ * RNK * DIM];   // 512 KB (pre-scaled by SCALING)

// ============================================================
// Kernel 1: fused gate MLP + adapter build.
//   Every block redundantly computes the tiny gating MLP for all 8
//   batches (LN -> 60-ReLU -> 4 -> softmax), then builds its slice of
//   A = gate @ Wa^T and B = SCALING * gate @ Wb^T.
//   grid: 64 blocks x 512 threads covers 2*16384 elements, 8 batches each.
// ============================================================
__global__ __launch_bounds__(512)
void gate_ab_kernel(const float* __restrict__ ctr,
                    const float* __restrict__ gamma,
                    const float* __restrict__ beta,
                    const float* __restrict__ W1,
                    const float* __restrict__ b1,
                    const float* __restrict__ W2,
                    const float* __restrict__ b2,
                    const float* __restrict__ Wa,
                    const float* __restrict__ Wb) {
    __shared__ float z_s[BSZ][32];
    __shared__ float h_s[BSZ][60];
    __shared__ float gate_s[BSZ][4];

    int warp = threadIdx.x >> 5;
    int lane = threadIdx.x & 31;

    // ---- gate MLP: warp w handles batch w (warps 8..15 idle here) ----
    if (warp < BSZ) {
        int w = warp;
        float v = ctr[w * 32 + lane];
        float m = v;
        #pragma unroll
        for (int off = 16; off; off >>= 1) m += __shfl_xor_sync(0xffffffffu, m, off);
        m *= (1.0f / 32.0f);
        float d = v - m;
        float s = d * d;
        #pragma unroll
        for (int off = 16; off; off >>= 1) s += __shfl_xor_sync(0xffffffffu, s, off);
        s *= (1.0f / 32.0f);
        float z = d * rsqrtf(s + 1e-5f) * gamma[lane] + beta[lane];
        z_s[w][lane] = z;
        __syncwarp();

        for (int j = lane; j < 60; j += 32) {
            float acc = b1[j];
            #pragma unroll
            for (int c = 0; c < 32; c++) acc += z_s[w][c] * W1[j * 32 + c];
            h_s[w][j] = fmaxf(acc, 0.0f);
        }
        __syncwarp();

        if (lane == 0) {
            float g[4];
            #pragma unroll
            for (int k = 0; k < 4; k++) {
                float acc = b2[k];
                for (int j = 0; j < 60; j++) acc += h_s[w][j] * W2[k * 60 + j];
                g[k] = acc;
            }
            float mx = fmaxf(fmaxf(g[0], g[1]), fmaxf(g[2], g[3]));
            float e0 = expf(g[0] - mx), e1 = expf(g[1] - mx);
            float e2 = expf(g[2] - mx), e3 = expf(g[3] - mx);
            float inv = 1.0f / (e0 + e1 + e2 + e3);
            gate_s[w][0] = e0 * inv;
            gate_s[w][1] = e1 * inv;
            gate_s[w][2] = e2 * inv;
            gate_s[w][3] = e3 * inv;
        }
    }
    __syncthreads();

    // ---- adapter build: one element (all 8 batches) per thread ----
    int idx = blockIdx.x * 512 + threadIdx.x;          // [0, 32768)
    int j = idx & (RNK * DIM - 1);
    bool isA = idx < RNK * DIM;
    const float4* Wrow = isA ? (const float4*)Wa : (const float4*)Wb;
    float* dst = isA ? g_A : g_B;
    float scale = isA ? 1.0f : SCALING;
    float4 w4 = Wrow[j];
    #pragma unroll
    for (int b = 0; b < BSZ; b++) {
        float4 g4 = *(const float4*)gate_s[b];          // smem broadcast
        dst[b * RNK * DIM + j] =
            scale * (w4.x * g4.x + w4.y * g4.y + w4.z * g4.z + w4.w * g4.w);
    }
}

// ============================================================
// Kernel 2: out[b,s,:] = (x[b,s,:] @ A[b]^T) @ B[b]   (SCALING in B)
//   256 blocks x 512 threads; block = (batch, 64-row tile).
//   A[b] staged once in 64 KB smem; rows processed in 2 chunks of 32,
//   2 rows/warp in phase 1 (shares every smem A read across 2 rows).
// ============================================================
extern __shared__ float As[];  // RNK*DIM floats = 64 KB

__global__ __launch_bounds__(512, 2)
void main_kernel(const float* __restrict__ x, float* __restrict__ out) {
    __shared__ float xa_s[ROWS_CHUNK][RNK];

    int b = blockIdx.x >> 5;            // / (SEQ/ROWS_PER_BLOCK = 32)
    int tile = blockIdx.x & 31;
    int row0 = tile * ROWS_PER_BLOCK;

    // ---- stage A[b] into smem (float4, coalesced, hits L2) ----
    {
        const float4* src = (const float4*)(g_A + b * RNK * DIM);
        float4* dst = (float4*)As;
        #pragma unroll
        for (int i = threadIdx.x; i < (RNK * DIM) / 4; i += 512) dst[i] = src[i];
    }
    __syncthreads();

    int warp = threadIdx.x >> 5;
    int lane = threadIdx.x & 31;
    const float4* Bb4 = (const float4*)(g_B + b * RNK * DIM);

    #pragma unroll
    for (int c = 0; c < CHUNKS; c++) {
        int r0 = row0 + c * ROWS_CHUNK;

        // ---- phase 1: warp handles 2 rows; xa[row][r] = x_row . A[r] ----
        {
            const float4* x40 =
                (const float4*)(x + ((size_t)b * SEQ + r0 + warp * 2) * DIM);
            const float4* x41 = x40 + DIM / 4;
            float acc0[RNK], acc1[RNK];
            #pragma unroll
            for (int r = 0; r < RNK; r++) { acc0[r] = 0.0f; acc1[r] = 0.0f; }

            #pragma unroll 4
            for (int k = 0; k < 16; k++) {
                int d4 = k * 32 + lane;                  // float4 idx in [0,512)
                float4 xv0 = __ldcs(x40 + d4);
                float4 xv1 = __ldcs(x41 + d4);
                #pragma unroll
                for (int r = 0; r < RNK; r++) {
                    float4 a = ((const float4*)(As + r * DIM))[d4];
                    acc0[r] += xv0.x * a.x + xv0.y * a.y + xv0.z * a.z + xv0.w * a.w;
                    acc1[r] += xv1.x * a.x + xv1.y * a.y + xv1.z * a.z + xv1.w * a.w;
                }
            }
            #pragma unroll
            for (int r = 0; r < RNK; r++) {
                #pragma unroll
                for (int off = 16; off; off >>= 1) {
                    acc0[r] += __shfl_xor_sync(0xffffffffu, acc0[r], off);
                    acc1[r] += __shfl_xor_sync(0xffffffffu, acc1[r], off);
                }
            }
            if (lane == 0) {
                #pragma unroll
                for (int r = 0; r < RNK; r++) {
                    xa_s[warp * 2 + 0][r] = acc0[r];
                    xa_s[warp * 2 + 1][r] = acc1[r];
                }
            }
        }
        __syncthreads();

        // ---- phase 2: thread owns 4 out cols; B reg-tiled; 32 rows ----
        {
            float4 Br[RNK];
            #pragma unroll
            for (int r = 0; r < RNK; r++)
                Br[r] = Bb4[r * (DIM / 4) + threadIdx.x];

            #pragma unroll
            for (int i = 0; i < ROWS_CHUNK; i++) {
                float4 o = make_float4(0.f, 0.f, 0.f, 0.f);
                #pragma unroll
                for (int r = 0; r < RNK; r++) {
                    float s = xa_s[i][r];
                    o.x += s * Br[r].x;
                    o.y += s * Br[r].y;
                    o.z += s * Br[r].z;
                    o.w += s * Br[r].w;
                }
                __stcs((float4*)(out + ((size_t)b * SEQ + r0 + i) * DIM) + threadIdx.x, o);
            }
        }
        __syncthreads();   // protect xa_s before next chunk
    }
}

// ============================================================
// launcher
// ============================================================
extern "C" void kernel_launch(void* const* d_in, const int* in_sizes, int n_in,
                              void* d_out, int out_size) {
    const float* x     = (const float*)d_in[0];
    const float* ctr   = (const float*)d_in[1];
    const float* gamma = (const float*)d_in[2];
    const float* beta  = (const float*)d_in[3];
    const float* W1    = (const float*)d_in[4];
    const float* b1    = (const float*)d_in[5];
    const float* W2    = (const float*)d_in[6];
    const float* b2    = (const float*)d_in[7];
    const float* Wa    = (const float*)d_in[8];
    const float* Wb    = (const float*)d_in[9];
    float* out = (float*)d_out;

    static bool attr_set = false;
    if (!attr_set) {
        cudaFuncSetAttribute(main_kernel,
                             cudaFuncAttributeMaxDynamicSharedMemorySize,
                             RNK * DIM * (int)sizeof(float));
        attr_set = true;
    }

    gate_ab_kernel<<<(2 * RNK * DIM) / 512, 512>>>(ctr, gamma, beta,
                                                   W1, b1, W2, b2, Wa, Wb);
    main_kernel<<<BSZ * (SEQ / ROWS_PER_BLOCK), 512,
                  RNK * DIM * sizeof(float)>>>(x, out);
}